// round 5
// baseline (speedup 1.0000x reference)
#include <cuda_runtime.h>
#include <cuda_bf16.h>
#include <cstdint>

#define B_ 32
#define L_ 256
#define D_ 768
#define KL 51             // NUM_LABELS + 1
#define KP 52             // padded inner pitch (bf16 rows 4B-aligned)
#define NPAD 2688         // 21*128 >= KP*KL = 2652
#define M_ 8192           // B_*L_

// ---------------- device scratch (allocation-free rule) ----------------
__device__ __nv_bfloat16 g_xb[M_ * D_];          // x in bf16
__device__ __nv_bfloat16 g_fW[NPAD * D_];        // fused (trans+state) weights, row c' = j*KP+i
__device__ float         g_fb[NPAD];             // fused bias
__device__ __nv_bfloat16 g_expE[L_ * B_ * NPAD]; // exp(energy), [t][b][c'=j*KP+i]
__device__ float         g_partial[B_];

// ---------------- helpers ----------------
__device__ __forceinline__ uint32_t smem_u32(const void* p) {
  return (uint32_t)__cvta_generic_to_shared(p);
}
__device__ __forceinline__ void cp_async16(uint32_t saddr, const void* gaddr) {
  asm volatile("cp.async.cg.shared.global [%0], [%1], 16;" :: "r"(saddr), "l"(gaddr));
}
__device__ __forceinline__ void cp_commit() {
  asm volatile("cp.async.commit_group;");
}

__device__ __forceinline__ void ldsm4(uint32_t* r, uint32_t addr) {
  asm volatile("ldmatrix.sync.aligned.m8n8.x4.shared.b16 {%0,%1,%2,%3}, [%4];"
               : "=r"(r[0]), "=r"(r[1]), "=r"(r[2]), "=r"(r[3]) : "r"(addr));
}
__device__ __forceinline__ void mma16816(float* d, const uint32_t* a, const uint32_t* b) {
  asm volatile(
      "mma.sync.aligned.m16n8k16.row.col.f32.bf16.bf16.f32 "
      "{%0,%1,%2,%3}, {%4,%5,%6,%7}, {%8,%9}, {%0,%1,%2,%3};"
      : "+f"(d[0]), "+f"(d[1]), "+f"(d[2]), "+f"(d[3])
      : "r"(a[0]), "r"(a[1]), "r"(a[2]), "r"(a[3]), "r"(b[0]), "r"(b[1]));
}

// FFMA-only exp (avoids MUFU bottleneck). |x| small, guaranteed by data.
__device__ __forceinline__ float fexp(float x) {
  float y = x * 1.44269504f;
  int ki = __float2int_rn(y);
  float f = y - (float)ki;
  float p = 1.53533619e-4f;
  p = fmaf(p, f, 1.33988744e-3f);
  p = fmaf(p, f, 9.61843745e-3f);
  p = fmaf(p, f, 5.55033250e-2f);
  p = fmaf(p, f, 2.40226478e-1f);
  p = fmaf(p, f, 6.93147203e-1f);
  p = fmaf(p, f, 1.0f);
  return p * __int_as_float((ki + 127) << 23);
}

// ---------------- kernel 1: convert x to bf16 ----------------
__global__ __launch_bounds__(256) void conv_x_kernel(const float* __restrict__ x) {
  int idx = blockIdx.x * 256 + threadIdx.x;     // per 4 elements
  float4 v = *(const float4*)(x + (size_t)idx * 4);
  __nv_bfloat162 lo = __floats2bfloat162_rn(v.x, v.y);
  __nv_bfloat162 hi = __floats2bfloat162_rn(v.z, v.w);
  *(__nv_bfloat162*)&g_xb[(size_t)idx * 4]     = lo;
  *(__nv_bfloat162*)&g_xb[(size_t)idx * 4 + 2] = hi;
}

// ---------------- kernel 2: build fused transposed weights ----------------
// c' = j*KP + i  (i = from-label, j = to-label).  fW[c'] = tW[i*KL+j] + sW[j]
__global__ __launch_bounds__(256) void prep_fw_kernel(
    const float* __restrict__ tW, const float* __restrict__ tb,
    const float* __restrict__ sW, const float* __restrict__ sb) {
  int e = blockIdx.x * 256 + threadIdx.x;       // over NPAD*D_
  int c = e / D_, d = e - c * D_;
  int j = c / KP, i = c - j * KP;
  bool valid = (j < KL) && (i < KL);
  float w = 0.f;
  if (valid) w = tW[(size_t)(i * KL + j) * D_ + d] + sW[(size_t)j * D_ + d];
  g_fW[(size_t)c * D_ + d] = __float2bfloat16(w);
  if (d == 0) g_fb[c] = valid ? (tb[i * KL + j] + sb[j]) : 0.f;
}

// ---------------- kernel 3: HMMA bf16 GEMM + exp epilogue ----------------
// smem: 2 stages x (A 128x32 @ pitch 80B = 10240B, B same) = 40960B
#define ROWP 80
#define STG  20480
#define BOFF 10240
#define NCHUNK 24          // 768 / 32

static __device__ __forceinline__ void load_chunk(uint32_t sb, int st, int rm,
                                                  int cn, int kt, int tid) {
  uint32_t base = sb + st * STG;
#pragma unroll
  for (int q = 0; q < 2; q++) {
    int idx = tid + q * 256;           // 0..511
    int row = idx >> 2, seg = idx & 3;
    cp_async16(base + row * ROWP + seg * 16,
               &g_xb[(size_t)(rm + row) * D_ + kt + seg * 8]);
  }
#pragma unroll
  for (int q = 0; q < 2; q++) {
    int idx = tid + q * 256;
    int row = idx >> 2, seg = idx & 3;
    cp_async16(base + BOFF + row * ROWP + seg * 16,
               &g_fW[(size_t)(cn + row) * D_ + kt + seg * 8]);
  }
  cp_commit();
}

__global__ __launch_bounds__(256, 2) void gemm_energy_kernel(
    const float* __restrict__ mask) {
  __shared__ __align__(128) char smem[2 * STG];
  uint32_t sb = smem_u32(smem);
  int tid = threadIdx.x, wid = tid >> 5, l = tid & 31;
  int cn = blockIdx.x * 128, rm = blockIdx.y * 128;
  int wr = wid & 3, wc = wid >> 2;

  float acc[2][8][4];
#pragma unroll
  for (int mi = 0; mi < 2; mi++)
#pragma unroll
    for (int ni = 0; ni < 8; ni++)
#pragma unroll
      for (int q = 0; q < 4; q++) acc[mi][ni][q] = 0.f;

  load_chunk(sb, 0, rm, cn, 0, tid);
  load_chunk(sb, 1, rm, cn, 32, tid);

  // ldmatrix lane offsets (conflict-free: pitch 80B -> bank = row*5 mod 8)
  uint32_t a_off = (l & 15) * ROWP + (l >> 4) * 16;
  uint32_t b_off = ((l >> 4) * 8 + (l & 7)) * ROWP + ((l >> 3) & 1) * 16;

  for (int c = 0; c < NCHUNK; c++) {
    int st = c & 1;
    asm volatile("cp.async.wait_group 1;" ::: "memory");
    __syncthreads();
    uint32_t aBase = sb + st * STG + wr * 32 * ROWP + a_off;
    uint32_t bBase = sb + st * STG + BOFF + wc * 64 * ROWP + b_off;
#pragma unroll
    for (int ks = 0; ks < 2; ks++) {
      uint32_t af[2][4], bf[4][4];
      ldsm4(af[0], aBase + ks * 32);
      ldsm4(af[1], aBase + 16 * ROWP + ks * 32);
#pragma unroll
      for (int np = 0; np < 4; np++)
        ldsm4(bf[np], bBase + np * 16 * ROWP + ks * 32);
#pragma unroll
      for (int mi = 0; mi < 2; mi++)
#pragma unroll
        for (int ni = 0; ni < 8; ni++)
          mma16816(acc[mi][ni], af[mi], &bf[ni >> 1][(ni & 1) * 2]);
    }
    __syncthreads();
    if (c + 2 < NCHUNK) load_chunk(sb, st, rm, cn, (c + 2) * 32, tid);
  }

  // Epilogue: E = acc + fb, *mask, exp -> bf16 transposed store
  int tq = l >> 2, tr = (l & 3) * 2;
#pragma unroll
  for (int mi = 0; mi < 2; mi++) {
    int r0 = rm + wr * 32 + mi * 16 + tq;
    int r1 = r0 + 8;
    float mv0 = __ldg(mask + r0), mv1 = __ldg(mask + r1);
    size_t d0row = (size_t)((r0 & (L_ - 1)) * B_ + (r0 >> 8)) * NPAD;
    size_t d1row = (size_t)((r1 & (L_ - 1)) * B_ + (r1 >> 8)) * NPAD;
#pragma unroll
    for (int ni = 0; ni < 8; ni++) {
      int c0 = cn + wc * 64 + ni * 8 + tr;
      float2 fb2 = *(const float2*)&g_fb[c0];
      float* a = acc[mi][ni];
      float e00 = (a[0] + fb2.x) * mv0, e01 = (a[1] + fb2.y) * mv0;
      float e10 = (a[2] + fb2.x) * mv1, e11 = (a[3] + fb2.y) * mv1;
      __nv_bfloat162 p0 = __floats2bfloat162_rn(fexp(e00), fexp(e01));
      __nv_bfloat162 p1 = __floats2bfloat162_rn(fexp(e10), fexp(e11));
      *(__nv_bfloat162*)&g_expE[d0row + c0] = p0;
      *(__nv_bfloat162*)&g_expE[d1row + c0] = p1;
    }
  }
}

// ---------------- kernel 4: CRF forward scan (linear-space, anchored) -----
#define NCHK (NPAD * 2 / 16)   // 336 cp.async chunks per tile

__global__ __launch_bounds__(128) void crf_scan_kernel(
    const float* __restrict__ mask, const int* __restrict__ target) {
  __shared__ __align__(16) __nv_bfloat16 tile[2][NPAD];
  __shared__ float s_P[64];
  __shared__ float s_rcp;
  __shared__ float s_mask[L_];
  __shared__ int   s_tgt[L_];
  int b = blockIdx.x, tid = threadIdx.x;
  for (int i = tid; i < L_; i += 128) {
    s_mask[i] = mask[b * L_ + i];
    s_tgt[i]  = target[b * L_ + i];
  }
  if (tid == 0) s_rcp = 1.0f;
  if (tid < 64) s_P[tid] = 0.f;

  {  // prefetch tile t=1
    const __nv_bfloat16* src = &g_expE[(size_t)(1 * B_ + b) * NPAD];
    uint32_t dst = smem_u32(&tile[1][0]);
    for (int ch = tid; ch < NCHK; ch += 128)
      cp_async16(dst + ch * 16, src + ch * 8);
    cp_commit();
  }
  __syncthreads();

  float Pj = 0.f, te = 0.f, shift = 0.f, anchor = 1.f;
  int prev = 0;
  {
    const __nv_bfloat16* e0 = &g_expE[(size_t)b * NPAD];
    if (tid < KL) Pj = __bfloat162float(e0[tid * KP + (KL - 1)]);
    if (tid == 0) {
      int tg = s_tgt[0];
      te = __logf(__bfloat162float(e0[tg * KP + (KL - 1)]));
      prev = ((int)s_mask[0] != 0) ? tg : (KL - 1);
    }
  }

  for (int t = 1; t < L_; t++) {
    const __nv_bfloat16* tl = tile[t & 1];
    if (t + 1 < L_) {
      const __nv_bfloat16* src = &g_expE[(size_t)((t + 1) * B_ + b) * NPAD];
      uint32_t dst = smem_u32(&tile[(t + 1) & 1][0]);
      for (int ch = tid; ch < NCHK; ch += 128)
        cp_async16(dst + ch * 16, src + ch * 8);
    }
    cp_commit();

    float rcp = s_rcp;
    if (tid < 64) {
      Pj *= rcp;
      s_P[tid] = Pj;                       // tid>=KL stays 0
    }
    if (tid == 0) shift += __logf(anchor);
    asm volatile("cp.async.wait_group 1;" ::: "memory");
    __syncthreads();                        // s_P + tile t ready

    if (tid < KL) {
      const uint32_t* row = (const uint32_t*)(tl + tid * KP);  // 4B aligned
      float acc = 0.f;
#pragma unroll
      for (int k = 0; k < 26; k++) {
        uint32_t u = row[k];
        float lo = __uint_as_float(u << 16);
        float hi = __uint_as_float(u & 0xFFFF0000u);
        acc = fmaf(s_P[2 * k], lo, acc);
        acc = fmaf(s_P[2 * k + 1], hi, acc);
      }
      if (s_mask[t] != 0.f) Pj = acc;
    }
    if (tid == 0) {
      float ev = __bfloat162float(tl[s_tgt[t] * KP + prev]);
      te += __logf(ev);
      if ((int)s_mask[t] != 0) prev = s_tgt[t];
      anchor = Pj;                          // thread0 owns j=0
      s_rcp = 1.0f / Pj;
    }
    __syncthreads();
  }

  // loss_b = shift + log(sum_j P_j) - te
  if (tid < 64) {
    float v = Pj;
#pragma unroll
    for (int off = 16; off > 0; off >>= 1)
      v += __shfl_xor_sync(0xffffffffu, v, off);
    if ((tid & 31) == 0) s_P[tid >> 5] = v;
  }
  __syncthreads();
  if (tid == 0)
    g_partial[b] = shift + __logf(s_P[0] + s_P[1]) - te;
}

// ---------------- kernel 5: mean ----------------
__global__ void reduce_kernel(float* out) {
  int tid = threadIdx.x;
  float v = (tid < B_) ? g_partial[tid] : 0.f;
#pragma unroll
  for (int off = 16; off > 0; off >>= 1)
    v += __shfl_xor_sync(0xffffffffu, v, off);
  if (tid == 0) out[0] = v * (1.f / B_);
}

// ---------------------------------------------------------------------------
extern "C" void kernel_launch(void* const* d_in, const int* in_sizes, int n_in,
                              void* d_out, int out_size) {
  const float* x      = (const float*)d_in[0];
  const float* mask   = (const float*)d_in[1];
  const int*   target = (const int*)d_in[2];
  const float* sW     = (const float*)d_in[3];
  const float* sb     = (const float*)d_in[4];
  const float* tW     = (const float*)d_in[5];
  const float* tb     = (const float*)d_in[6];

  conv_x_kernel<<<(M_ * D_ / 4) / 256, 256>>>(x);
  prep_fw_kernel<<<(NPAD * D_) / 256, 256>>>(tW, tb, sW, sb);
  dim3 gg(NPAD / 128, M_ / 128);
  gemm_energy_kernel<<<gg, 256>>>(mask);
  crf_scan_kernel<<<B_, 128>>>(mask, target);
  reduce_kernel<<<1, 32>>>((float*)d_out);
}

// round 6
// speedup vs baseline: 1.1668x; 1.1668x over previous
#include <cuda_runtime.h>
#include <cuda_bf16.h>
#include <cstdint>

#define B_ 32
#define L_ 256
#define D_ 768
#define KL 51             // NUM_LABELS + 1
#define KP 52             // padded inner pitch
#define NPAD 2688         // fW rows (21*128), GEMM N extent
#define NPF 2656          // expE row pitch in f32 (>= KP*KL=2652, 16B multiple)
#define M_ 8192           // B_*L_

// ---------------- device scratch (allocation-free rule) ----------------
__device__ __nv_bfloat16 g_xb[M_ * D_];          // x in bf16
__device__ __nv_bfloat16 g_fW[NPAD * D_];        // fused (trans+state) weights, row c' = j*KP+i
__device__ float         g_fb[NPAD];             // fused bias
__device__ float         g_expE[(size_t)M_ * NPF]; // exp(energy) f32, [t][b][c'=j*KP+i]
__device__ float         g_partial[B_];

// ---------------- helpers ----------------
__device__ __forceinline__ uint32_t smem_u32(const void* p) {
  return (uint32_t)__cvta_generic_to_shared(p);
}
__device__ __forceinline__ void cp_async16(uint32_t saddr, const void* gaddr) {
  asm volatile("cp.async.cg.shared.global [%0], [%1], 16;" :: "r"(saddr), "l"(gaddr));
}
__device__ __forceinline__ void cp_commit() {
  asm volatile("cp.async.commit_group;");
}

__device__ __forceinline__ void ldsm4(uint32_t* r, uint32_t addr) {
  asm volatile("ldmatrix.sync.aligned.m8n8.x4.shared.b16 {%0,%1,%2,%3}, [%4];"
               : "=r"(r[0]), "=r"(r[1]), "=r"(r[2]), "=r"(r[3]) : "r"(addr));
}
__device__ __forceinline__ void mma16816(float* d, const uint32_t* a, const uint32_t* b) {
  asm volatile(
      "mma.sync.aligned.m16n8k16.row.col.f32.bf16.bf16.f32 "
      "{%0,%1,%2,%3}, {%4,%5,%6,%7}, {%8,%9}, {%0,%1,%2,%3};"
      : "+f"(d[0]), "+f"(d[1]), "+f"(d[2]), "+f"(d[3])
      : "r"(a[0]), "r"(a[1]), "r"(a[2]), "r"(a[3]), "r"(b[0]), "r"(b[1]));
}

// FFMA-only exp (avoids MUFU bottleneck). |x| small, guaranteed by data.
__device__ __forceinline__ float fexp(float x) {
  float y = x * 1.44269504f;
  int ki = __float2int_rn(y);
  float f = y - (float)ki;
  float p = 1.53533619e-4f;
  p = fmaf(p, f, 1.33988744e-3f);
  p = fmaf(p, f, 9.61843745e-3f);
  p = fmaf(p, f, 5.55033250e-2f);
  p = fmaf(p, f, 2.40226478e-1f);
  p = fmaf(p, f, 6.93147203e-1f);
  p = fmaf(p, f, 1.0f);
  return p * __int_as_float((ki + 127) << 23);
}

// ---------------- kernel 1: convert x to bf16 ----------------
__global__ __launch_bounds__(256) void conv_x_kernel(const float* __restrict__ x) {
  int idx = blockIdx.x * 256 + threadIdx.x;     // per 4 elements
  float4 v = *(const float4*)(x + (size_t)idx * 4);
  __nv_bfloat162 lo = __floats2bfloat162_rn(v.x, v.y);
  __nv_bfloat162 hi = __floats2bfloat162_rn(v.z, v.w);
  *(__nv_bfloat162*)&g_xb[(size_t)idx * 4]     = lo;
  *(__nv_bfloat162*)&g_xb[(size_t)idx * 4 + 2] = hi;
}

// ---------------- kernel 2: build fused transposed weights ----------------
// c' = j*KP + i  (i = from-label, j = to-label).  fW[c'] = tW[i*KL+j] + sW[j]
__global__ __launch_bounds__(256) void prep_fw_kernel(
    const float* __restrict__ tW, const float* __restrict__ tb,
    const float* __restrict__ sW, const float* __restrict__ sb) {
  int e = blockIdx.x * 256 + threadIdx.x;       // over NPAD*D_
  int c = e / D_, d = e - c * D_;
  int j = c / KP, i = c - j * KP;
  bool valid = (j < KL) && (i < KL);
  float w = 0.f;
  if (valid) w = tW[(size_t)(i * KL + j) * D_ + d] + sW[(size_t)j * D_ + d];
  g_fW[(size_t)c * D_ + d] = __float2bfloat16(w);
  if (d == 0) g_fb[c] = valid ? (tb[i * KL + j] + sb[j]) : 0.f;
}

// ---------------- kernel 3: HMMA bf16 GEMM + exp epilogue ----------------
#define ROWP 80
#define STG  20480
#define BOFF 10240
#define NCHUNK 24          // 768 / 32

static __device__ __forceinline__ void load_chunk(uint32_t sb, int st, int rm,
                                                  int cn, int kt, int tid) {
  uint32_t base = sb + st * STG;
#pragma unroll
  for (int q = 0; q < 2; q++) {
    int idx = tid + q * 256;           // 0..511
    int row = idx >> 2, seg = idx & 3;
    cp_async16(base + row * ROWP + seg * 16,
               &g_xb[(size_t)(rm + row) * D_ + kt + seg * 8]);
  }
#pragma unroll
  for (int q = 0; q < 2; q++) {
    int idx = tid + q * 256;
    int row = idx >> 2, seg = idx & 3;
    cp_async16(base + BOFF + row * ROWP + seg * 16,
               &g_fW[(size_t)(cn + row) * D_ + kt + seg * 8]);
  }
  cp_commit();
}

__global__ __launch_bounds__(256, 2) void gemm_energy_kernel(
    const float* __restrict__ mask) {
  __shared__ __align__(128) char smem[2 * STG];
  uint32_t sb = smem_u32(smem);
  int tid = threadIdx.x, wid = tid >> 5, l = tid & 31;
  int cn = blockIdx.x * 128, rm = blockIdx.y * 128;
  int wr = wid & 3, wc = wid >> 2;

  float acc[2][8][4];
#pragma unroll
  for (int mi = 0; mi < 2; mi++)
#pragma unroll
    for (int ni = 0; ni < 8; ni++)
#pragma unroll
      for (int q = 0; q < 4; q++) acc[mi][ni][q] = 0.f;

  load_chunk(sb, 0, rm, cn, 0, tid);
  load_chunk(sb, 1, rm, cn, 32, tid);

  // ldmatrix lane offsets (conflict-free: pitch 80B -> bank = row*5 mod 8)
  uint32_t a_off = (l & 15) * ROWP + (l >> 4) * 16;
  uint32_t b_off = ((l >> 4) * 8 + (l & 7)) * ROWP + ((l >> 3) & 1) * 16;

  for (int c = 0; c < NCHUNK; c++) {
    int st = c & 1;
    asm volatile("cp.async.wait_group 1;" ::: "memory");
    __syncthreads();
    uint32_t aBase = sb + st * STG + wr * 32 * ROWP + a_off;
    uint32_t bBase = sb + st * STG + BOFF + wc * 64 * ROWP + b_off;
#pragma unroll
    for (int ks = 0; ks < 2; ks++) {
      uint32_t af[2][4], bf[4][4];
      ldsm4(af[0], aBase + ks * 32);
      ldsm4(af[1], aBase + 16 * ROWP + ks * 32);
#pragma unroll
      for (int np = 0; np < 4; np++)
        ldsm4(bf[np], bBase + np * 16 * ROWP + ks * 32);
#pragma unroll
      for (int mi = 0; mi < 2; mi++)
#pragma unroll
        for (int ni = 0; ni < 8; ni++)
          mma16816(acc[mi][ni], af[mi], &bf[ni >> 1][(ni & 1) * 2]);
    }
    __syncthreads();
    if (c + 2 < NCHUNK) load_chunk(sb, st, rm, cn, (c + 2) * 32, tid);
  }

  // Epilogue: E = acc + fb, *mask, exp -> f32 transposed store
  int tq = l >> 2, tr = (l & 3) * 2;
#pragma unroll
  for (int mi = 0; mi < 2; mi++) {
    int r0 = rm + wr * 32 + mi * 16 + tq;
    int r1 = r0 + 8;
    float mv0 = __ldg(mask + r0), mv1 = __ldg(mask + r1);
    size_t d0row = (size_t)((r0 & (L_ - 1)) * B_ + (r0 >> 8)) * NPF;
    size_t d1row = (size_t)((r1 & (L_ - 1)) * B_ + (r1 >> 8)) * NPF;
#pragma unroll
    for (int ni = 0; ni < 8; ni++) {
      int c0 = cn + wc * 64 + ni * 8 + tr;
      if (c0 < NPF) {
        float2 fb2 = *(const float2*)&g_fb[c0];
        float* a = acc[mi][ni];
        float2 p0 = make_float2(fexp((a[0] + fb2.x) * mv0),
                                fexp((a[1] + fb2.y) * mv0));
        float2 p1 = make_float2(fexp((a[2] + fb2.x) * mv1),
                                fexp((a[3] + fb2.y) * mv1));
        *(float2*)&g_expE[d0row + c0] = p0;
        *(float2*)&g_expE[d1row + c0] = p1;
      }
    }
  }
}

// ---------------- kernel 4: CRF forward scan (f32, deferred logs) ---------
#define NSTG 4
#define NCHK (NPF / 4)     // 664 cp.async 16B chunks per tile

__global__ __launch_bounds__(128) void crf_scan_kernel(
    const float* __restrict__ mask, const int* __restrict__ target) {
  __shared__ __align__(16) float tile[NSTG][NPF];   // 42496 B
  __shared__ __align__(16) float s_P[64];
  __shared__ float s_anch[L_];
  __shared__ float s_mask[L_];
  __shared__ int   s_tgt[L_];
  __shared__ int   s_prev[L_];
  __shared__ float s_red[8];
  int b = blockIdx.x, tid = threadIdx.x;

  for (int i = tid; i < L_; i += 128) {
    s_mask[i] = mask[b * L_ + i];
    s_tgt[i]  = target[b * L_ + i];
  }
  // prefetch tiles t=1..4 (4 commit groups)
#pragma unroll
  for (int s = 1; s <= NSTG; s++) {
    const float* src = &g_expE[(size_t)(s * B_ + b) * NPF];
    uint32_t dst = smem_u32(&tile[s & (NSTG - 1)][0]);
    for (int ch = tid; ch < NCHK; ch += 128)
      cp_async16(dst + ch * 16, src + ch * 4);
    cp_commit();
  }
  __syncthreads();

  if (tid == 0) {                       // prev chain (mask/target only)
    int pv = ((int)s_mask[0] != 0) ? s_tgt[0] : (KL - 1);
    s_prev[0] = pv;
    for (int t = 1; t < L_; t++) {
      if ((int)s_mask[t] != 0) pv = s_tgt[t];
      s_prev[t] = pv;
    }
  }
  __syncthreads();

  // target-energy gather: fully parallel, off the critical path
  float nloc = 0.f;                      // accumulates (shift - te) pieces
  for (int t = tid; t < L_; t += 128) {
    int row = (t == 0) ? (KL - 1) : s_prev[t - 1];
    float ev = g_expE[(size_t)(t * B_ + b) * NPF + s_tgt[t] * KP + row];
    nloc -= __logf(ev);                  // masked steps: ev==1 -> 0
  }

  // init partition (linear space): P_j = expE[0][K-1, j]
  float Pj = 0.f;
  if (tid < KL) Pj = g_expE[(size_t)b * NPF + tid * KP + (KL - 1)];
  if (tid < 64) s_P[tid] = (tid < KL) ? Pj : 0.f;

  for (int t = 1; t < L_; t++) {
    asm volatile("cp.async.wait_group 3;" ::: "memory");
    __syncthreads();                     // tile[t&3] ready; s_P visible
    const float* tl = tile[t & (NSTG - 1)];
    float anchor = s_P[0];               // LDS broadcast
    float m = s_mask[t];
    if (tid < KL) {
      float r = __fdividef(1.f, anchor);
      const float4* row = (const float4*)(tl + tid * KP);
      const float4* w = (const float4*)s_P;
      float a0 = 0.f, a1 = 0.f, a2 = 0.f, a3 = 0.f;
#pragma unroll
      for (int k = 0; k < 13; k++) {
        float4 mv = row[k];
        float4 wv = w[k];
        a0 = fmaf(wv.x, mv.x, a0);
        a1 = fmaf(wv.y, mv.y, a1);
        a2 = fmaf(wv.z, mv.z, a2);
        a3 = fmaf(wv.w, mv.w, a3);
      }
      float acc = ((a0 + a1) + (a2 + a3)) * r;
      if (m != 0.f) Pj = acc;
    }
    if (tid == 0) s_anch[t] = (m != 0.f) ? anchor : 1.f;
    __syncthreads();                     // tile/s_P reads complete
    if (tid < 64) s_P[tid] = (tid < KL) ? Pj : 0.f;
    if (t + NSTG < L_) {                 // refill slot just freed
      const float* src = &g_expE[(size_t)((t + NSTG) * B_ + b) * NPF];
      uint32_t dst = smem_u32(&tile[t & (NSTG - 1)][0]);
      for (int ch = tid; ch < NCHK; ch += 128)
        cp_async16(dst + ch * 16, src + ch * 4);
      cp_commit();
    }
  }

  // shift = sum of log anchors (parallel)
  for (int t = tid; t < L_; t += 128)
    if (t >= 1) nloc += __logf(s_anch[t]);

  // combined block reduction: sum(P) and nloc
  float sumP = (tid < KL) ? Pj : 0.f;
#pragma unroll
  for (int off = 16; off > 0; off >>= 1) {
    sumP += __shfl_xor_sync(0xffffffffu, sumP, off);
    nloc += __shfl_xor_sync(0xffffffffu, nloc, off);
  }
  int wd = tid >> 5;
  if ((tid & 31) == 0) { s_red[wd] = sumP; s_red[4 + wd] = nloc; }
  __syncthreads();
  if (tid == 0) {
    float sp = s_red[0] + s_red[1];      // only warps 0,1 hold P
    float sh = s_red[4] + s_red[5] + s_red[6] + s_red[7];
    g_partial[b] = __logf(sp) + sh;
  }
}

// ---------------- kernel 5: mean ----------------
__global__ void reduce_kernel(float* out) {
  int tid = threadIdx.x;
  float v = (tid < B_) ? g_partial[tid] : 0.f;
#pragma unroll
  for (int off = 16; off > 0; off >>= 1)
    v += __shfl_xor_sync(0xffffffffu, v, off);
  if (tid == 0) out[0] = v * (1.f / B_);
}

// ---------------------------------------------------------------------------
extern "C" void kernel_launch(void* const* d_in, const int* in_sizes, int n_in,
                              void* d_out, int out_size) {
  const float* x      = (const float*)d_in[0];
  const float* mask   = (const float*)d_in[1];
  const int*   target = (const int*)d_in[2];
  const float* sW     = (const float*)d_in[3];
  const float* sb     = (const float*)d_in[4];
  const float* tW     = (const float*)d_in[5];
  const float* tb     = (const float*)d_in[6];

  conv_x_kernel<<<(M_ * D_ / 4) / 256, 256>>>(x);
  prep_fw_kernel<<<(NPAD * D_) / 256, 256>>>(tW, tb, sW, sb);
  dim3 gg(NPAD / 128, M_ / 128);
  gemm_energy_kernel<<<gg, 256>>>(mask);
  crf_scan_kernel<<<B_, 128>>>(mask, target);
  reduce_kernel<<<1, 32>>>((float*)d_out);
}